// round 4
// baseline (speedup 1.0000x reference)
#include <cuda_runtime.h>
#include <cuda_bf16.h>
#include <stdint.h>

#define MAXN 50000
#define MAXE 1600000
#define FEAT 128
#define HID 32
#define NOUT 64
#define ROWV 8   // HID floats = 8 float4 per row

// Scratch (device globals; allocation is forbidden). float4-typed => 16B aligned.
__device__ int    d_is32;                      // 1 if edge_index is int32
__device__ int    d_src[MAXE];
__device__ int    d_dst[MAXE];
__device__ float  d_dinv[MAXN];                // deg -> rsqrt(deg), in place
__device__ float4 d_g1[MAXN * ROWV];           // pre-scaled transform, layer 1
__device__ float4 d_agg1[MAXN * ROWV];
__device__ float4 d_g2[MAXN * ROWV];
__device__ float4 d_agg2[MAXN * ROWV];

// ---------------------------------------------------------------- dtype detect
__global__ void k_flag_reset() { d_is32 = 0; }

// If edge_index is int64 with values in [0,50000), every odd 32-bit word is 0.
// If it is int32, odd words are random indices -> almost surely nonzero.
__global__ void k_detect(const int* __restrict__ w, int nwords) {
    int acc = 0;
    for (int i = blockIdx.x * blockDim.x + threadIdx.x; 2 * i + 1 < nwords;
         i += gridDim.x * blockDim.x)
        acc |= w[2 * i + 1];
    if (acc) atomicOr(&d_is32, 1);
}

__global__ void k_extract(const void* __restrict__ ei, int E) {
    int e = blockIdx.x * blockDim.x + threadIdx.x;
    if (e >= E) return;
    if (d_is32) {
        const int* p = (const int*)ei;
        d_src[e] = p[e];
        d_dst[e] = p[E + e];
    } else {
        const long long* p = (const long long*)ei;
        d_src[e] = (int)p[e];
        d_dst[e] = (int)p[E + e];
    }
}

// ---------------------------------------------------------------- degree
__global__ void k_deg_init(int N) {
    int i = blockIdx.x * blockDim.x + threadIdx.x;
    if (i < N) d_dinv[i] = 1.0f;  // self loop
}

__global__ void k_deg_acc(int E) {
    int e = blockIdx.x * blockDim.x + threadIdx.x;
    if (e >= E) return;
    atomicAdd(&d_dinv[d_dst[e]], 1.0f);
}

__global__ void k_dinv(int N) {
    int i = blockIdx.x * blockDim.x + threadIdx.x;
    if (i < N) d_dinv[i] = rsqrtf(d_dinv[i]);
}

// ---------------------------------------------------------------- layer1 transform:
// g1 = (x @ W1) * dinv[row];  agg1 = 0
__global__ void k_transform1(const float* __restrict__ x,
                             const float* __restrict__ W1, int N) {
    __shared__ float Ws[FEAT * HID];  // 16 KB
    for (int i = threadIdx.x; i < FEAT * HID; i += blockDim.x) Ws[i] = W1[i];
    __syncthreads();

    int warp = (blockIdx.x * blockDim.x + threadIdx.x) >> 5;
    int lane = threadIdx.x & 31;
    if (warp >= N) return;
    int row = warp;

    float xv[4];
#pragma unroll
    for (int i = 0; i < 4; i++) xv[i] = x[row * FEAT + lane + i * 32];

    float acc = 0.f;
#pragma unroll
    for (int k = 0; k < FEAT; k++) {
        float xk = __shfl_sync(0xffffffffu, xv[k >> 5], k & 31);
        acc = fmaf(xk, Ws[k * HID + lane], acc);
    }
    float d = d_dinv[row];
    reinterpret_cast<float*>(d_g1)[row * HID + lane] = acc * d;
    reinterpret_cast<float*>(d_agg1)[row * HID + lane] = 0.f;
}

// ---------------------------------------------------------------- edge scatter:
// agg[dst] += g[src]   (rows of 32 floats; 8 threads/edge, float4 RED to L2)
__device__ __forceinline__ void scatter_body(const float4* __restrict__ g,
                                             float4* __restrict__ agg, int E) {
    int tid = blockIdx.x * blockDim.x + threadIdx.x;
    int e = tid >> 3;
    if (e >= E) return;
    int j = tid & 7;
    int src = __ldg(&d_src[e]);
    int dst = __ldg(&d_dst[e]);
    float4 v = __ldg(&g[src * ROWV + j]);
    unsigned long long gp =
        (unsigned long long)__cvta_generic_to_global(&agg[dst * ROWV + j]);
    asm volatile("red.global.add.v4.f32 [%0], {%1,%2,%3,%4};"
                 :: "l"(gp), "f"(v.x), "f"(v.y), "f"(v.z), "f"(v.w)
                 : "memory");
}

__global__ void k_scatter1(int E) { scatter_body(d_g1, d_agg1, E); }
__global__ void k_scatter2(int E) { scatter_body(d_g2, d_agg2, E); }

// ---------------------------------------------------------------- finalize1 + transform2:
// h1 = relu(dinv*(agg1+g1)+b1);  g2 = (h1 @ W2) * dinv;  agg2 = 0
__global__ void k_mid(const float* __restrict__ b1,
                      const float* __restrict__ W2, int N) {
    __shared__ float Ws[HID * HID];  // 4 KB
    for (int i = threadIdx.x; i < HID * HID; i += blockDim.x) Ws[i] = W2[i];
    __syncthreads();

    int warp = (blockIdx.x * blockDim.x + threadIdx.x) >> 5;
    int lane = threadIdx.x & 31;
    if (warp >= N) return;
    int row = warp;

    float d = d_dinv[row];
    float t = reinterpret_cast<const float*>(d_agg1)[row * HID + lane] +
              reinterpret_cast<const float*>(d_g1)[row * HID + lane];
    t = fmaxf(fmaf(t, d, b1[lane]), 0.f);  // h1[row][lane]

    float acc = 0.f;
#pragma unroll
    for (int k = 0; k < HID; k++) {
        float tk = __shfl_sync(0xffffffffu, t, k);
        acc = fmaf(tk, Ws[k * HID + lane], acc);
    }
    reinterpret_cast<float*>(d_g2)[row * HID + lane] = acc * d;
    reinterpret_cast<float*>(d_agg2)[row * HID + lane] = 0.f;
}

// ---------------------------------------------------------------- finalize2 + head:
// h2 = relu(dinv*(agg2+g2)+b2);  out = h2 @ Wout + bout  (64 cols -> 2 per lane)
__global__ void k_final(const float* __restrict__ b2,
                        const float* __restrict__ Wout,
                        const float* __restrict__ bout,
                        float* __restrict__ out, int N) {
    __shared__ float Ws[HID * NOUT];  // 8 KB
    for (int i = threadIdx.x; i < HID * NOUT; i += blockDim.x) Ws[i] = Wout[i];
    __syncthreads();

    int warp = (blockIdx.x * blockDim.x + threadIdx.x) >> 5;
    int lane = threadIdx.x & 31;
    if (warp >= N) return;
    int row = warp;

    float d = d_dinv[row];
    float t = reinterpret_cast<const float*>(d_agg2)[row * HID + lane] +
              reinterpret_cast<const float*>(d_g2)[row * HID + lane];
    t = fmaxf(fmaf(t, d, b2[lane]), 0.f);  // h2[row][lane]

    float acc0 = bout[lane];
    float acc1 = bout[lane + 32];
#pragma unroll
    for (int k = 0; k < HID; k++) {
        float tk = __shfl_sync(0xffffffffu, t, k);
        acc0 = fmaf(tk, Ws[k * NOUT + lane], acc0);
        acc1 = fmaf(tk, Ws[k * NOUT + lane + 32], acc1);
    }
    out[row * NOUT + lane] = acc0;
    out[row * NOUT + lane + 32] = acc1;
}

// ---------------------------------------------------------------- launch
extern "C" void kernel_launch(void* const* d_in, const int* in_sizes, int n_in,
                              void* d_out, int out_size) {
    const float* x = (const float*)d_in[0];
    const void* ei = d_in[1];
    const float* W1 = (const float*)d_in[2];
    const float* b1 = (const float*)d_in[3];
    const float* W2 = (const float*)d_in[4];
    const float* b2 = (const float*)d_in[5];
    const float* Wout = (const float*)d_in[6];
    const float* bout = (const float*)d_in[7];
    float* out = (float*)d_out;

    int N = in_sizes[0] / FEAT;     // 50000
    int E = in_sizes[1] / 2;        // 1600000

    const int TB = 256;
    // dtype detect + canonical index extraction (handles int32 or int64)
    k_flag_reset<<<1, 1>>>();
    k_detect<<<128, TB>>>((const int*)ei, 2 * E);
    k_extract<<<(E + TB - 1) / TB, TB>>>(ei, E);
    // degrees
    k_deg_init<<<(N + TB - 1) / TB, TB>>>(N);
    k_deg_acc<<<(E + TB - 1) / TB, TB>>>(E);
    k_dinv<<<(N + TB - 1) / TB, TB>>>(N);
    // layer 1
    k_transform1<<<(N * 32 + TB - 1) / TB, TB>>>(x, W1, N);
    {
        long long threads = (long long)E * ROWV;
        k_scatter1<<<(unsigned)((threads + TB - 1) / TB), TB>>>(E);
    }
    // layer 2
    k_mid<<<(N * 32 + TB - 1) / TB, TB>>>(b1, W2, N);
    {
        long long threads = (long long)E * ROWV;
        k_scatter2<<<(unsigned)((threads + TB - 1) / TB), TB>>>(E);
    }
    // head
    k_final<<<(N * 32 + TB - 1) / TB, TB>>>(b2, Wout, bout, out, N);
}